// round 17
// baseline (speedup 1.0000x reference)
#include <cuda_runtime.h>
#include <cuda_fp16.h>
#include <cstdint>
#include <cstddef>

// Problem constants
#define NTOK 4096   // B*L
#define HDIM 2048
#define EEXP 8
#define DFF  8192

// ---------------------------------------------------------------------------
// Scratch (device globals; no runtime allocation allowed)
// ---------------------------------------------------------------------------
__device__ __align__(256) __half g_xh[(size_t)NTOK * HDIM];
__device__ __align__(256) __half g_w1h[(size_t)DFF * HDIM];   // transposed [DFF, HDIM]
__device__ __align__(256) __half g_w2h[(size_t)HDIM * DFF];   // transposed [HDIM, DFF]
__device__ __align__(256) __half g_h1h[(size_t)NTOK * DFF];
__device__ __align__(256) float g_moe[(size_t)NTOK * HDIM];

// ---------------------------------------------------------------------------
// PTX helpers (family-agnostic sm_80+ ops; tcgen05 unavailable on this toolchain)
// ---------------------------------------------------------------------------
__device__ __forceinline__ uint32_t smem_u32(const void* p) {
    uint32_t a;
    asm("{ .reg .u64 t; cvta.to.shared.u64 t, %1; cvt.u32.u64 %0, t; }" : "=r"(a) : "l"(p));
    return a;
}
__device__ __forceinline__ void cp_async16(uint32_t dst, const void* src) {
    asm volatile("cp.async.cg.shared.global [%0], [%1], 16;" :: "r"(dst), "l"(src));
}
__device__ __forceinline__ void cp_commit() {
    asm volatile("cp.async.commit_group;" ::: "memory");
}
template <int N>
__device__ __forceinline__ void cp_wait() {
    asm volatile("cp.async.wait_group %0;" :: "n"(N) : "memory");
}
__device__ __forceinline__ void ldsm_x4(uint32_t* r, uint32_t addr) {
    asm volatile("ldmatrix.sync.aligned.m8n8.x4.shared.b16 {%0,%1,%2,%3}, [%4];"
                 : "=r"(r[0]), "=r"(r[1]), "=r"(r[2]), "=r"(r[3]) : "r"(addr));
}
__device__ __forceinline__ void mma_16816(float* d, const uint32_t* a, const uint32_t* b) {
    asm volatile("mma.sync.aligned.m16n8k16.row.col.f32.f16.f16.f32 "
                 "{%0,%1,%2,%3}, {%4,%5,%6,%7}, {%8,%9}, {%0,%1,%2,%3};"
                 : "+f"(d[0]), "+f"(d[1]), "+f"(d[2]), "+f"(d[3])
                 : "r"(a[0]), "r"(a[1]), "r"(a[2]), "r"(a[3]), "r"(b[0]), "r"(b[1]));
}

// ---------------------------------------------------------------------------
// Conversion kernel: w [K,N] fp32 row-major -> oh [N,K] fp16 (transposed)
// ---------------------------------------------------------------------------
__global__ __launch_bounds__(256) void transpose_half_kernel(const float* __restrict__ w,
                                                             __half* __restrict__ oh,
                                                             int K, int N)
{
    __shared__ float t[32][33];
    const int n0 = blockIdx.x * 32;
    const int k0 = blockIdx.y * 32;
    const int tx = threadIdx.x & 31;
    const int ty = threadIdx.x >> 5;   // 0..7
#pragma unroll
    for (int r = 0; r < 4; r++) {
        int kk = ty + r * 8;
        t[kk][tx] = w[(size_t)(k0 + kk) * N + n0 + tx];
    }
    __syncthreads();
#pragma unroll
    for (int r = 0; r < 4; r++) {
        int nn = ty + r * 8;
        oh[(size_t)(n0 + nn) * K + k0 + tx] = __float2half_rn(t[tx][nn]);
    }
}

// ---------------------------------------------------------------------------
// HGEMM via mma.sync: C[M,N] = op(A @ B^T) [+ Madd]
// A [M,K] fp16, B [N,K] fp16, single product, fp32 accumulate.
// CTA tile 128x128, BK=64 (128B rows, XOR swizzle), 2-stage cp.async
// (32 KB/stage -> 64 KB/CTA), 4 warps 2(M)x2(N), warp tile 64x64 (best
// smem-traffic/MAC: 0.0625 B/MAC), __launch_bounds__(128,3): THREE CTAs/SM
// (12 warps, reg cap 170) — smem crossbar no longer binds at this ratio.
// GELU=true: tanh-GELU, write fp16 Ch. Else write fp32 Cf (+Madd).
// ---------------------------------------------------------------------------
#define A_T_B   16384             // A tile: 128 rows x 128 B
#define B_T_B   16384             // B tile: 128 rows x 128 B
#define STAGE_B (A_T_B + B_T_B)   // 32 KB
#define OFF_BH  A_T_B
#define GROUP_N 16

__device__ __forceinline__ float gelu_tanh(float v)
{
    float inner = 0.7978845608028654f * (v + 0.044715f * v * v * v);
    return 0.5f * v * (1.0f + tanhf(inner));
}

template <bool GELU>
__global__ __launch_bounds__(128, 3) void hgemm_kernel(const __half* __restrict__ Ah,
                                                       const __half* __restrict__ Bh,
                                                       __half* __restrict__ Ch,
                                                       float* __restrict__ Cf,
                                                       const float* __restrict__ Madd,
                                                       int N, int K)
{
    extern __shared__ __align__(1024) char smem[];
    const uint32_t sm0 = smem_u32(smem);

    const int tid = threadIdx.x;
    const int lane = tid & 31;
    const int wid = tid >> 5;
    const int wm = wid & 1;        // M warp coord (2) -> 64 rows each
    const int wn = wid >> 1;       // N warp coord (2) -> 64 cols each
    const int NK = K >> 6;         // K / 64

    // raster swizzle: consecutive CTAs walk M within a GROUP_N-wide N band
    const int tilesM = NTOK / 128;
    const int per_group = GROUP_N * tilesM;
    const int grp = blockIdx.x / per_group;
    const int rem = blockIdx.x % per_group;
    const int bx = grp * GROUP_N + (rem % GROUP_N);
    const int by = rem / GROUP_N;

    // ldmatrix lane decomposition
    const int g = lane >> 3;
    const int lr = lane & 7;
    const int a_row = ((g & 1) << 3) + lr;
    const int a_c = g >> 1;
    const int b_row = ((g >> 1) << 3) + lr;
    const int b_c = g & 1;

    // global load coords: thread t loads rows ld_r+16*it, 16B chunk ld_c
    const int ld_r = tid >> 3;     // 0..15
    const int ld_c = tid & 7;      // 16B chunk in 128B row
    const __half* gA = Ah + (size_t)(by * 128 + ld_r) * K + ld_c * 8;
    const __half* gB = Bh + (size_t)(bx * 128 + ld_r) * K + ld_c * 8;

    auto load_stage = [&](int j, int slot) {
        uint32_t sb = sm0 + slot * STAGE_B;
        size_t ko = (size_t)j * 64;   // halves
        {
            const __half* src = gA + ko;
#pragma unroll
            for (int it = 0; it < 8; it++) {          // 128 rows / 16
                int row = ld_r + it * 16;
                uint32_t d = sb + row * 128 + ((ld_c ^ (row & 7)) << 4);
                cp_async16(d, src + (size_t)it * 16 * K);
            }
        }
        {
            const __half* src = gB + ko;
            uint32_t db = sb + OFF_BH;
#pragma unroll
            for (int it = 0; it < 8; it++) {
                int row = ld_r + it * 16;
                uint32_t d = db + row * 128 + ((ld_c ^ (row & 7)) << 4);
                cp_async16(d, src + (size_t)it * 16 * K);
            }
        }
    };

    float acc[4][8][4];
#pragma unroll
    for (int mt = 0; mt < 4; mt++)
#pragma unroll
        for (int nt = 0; nt < 8; nt++)
#pragma unroll
            for (int q = 0; q < 4; q++) acc[mt][nt][q] = 0.f;

    load_stage(0, 0);
    cp_commit();

    uint32_t ah[4][4], bh[4][4];

    for (int i = 0; i < NK; i++) {
        cp_wait<0>();                 // chunk i resident
        __syncthreads();              // readers of the other slot done

        if (i + 1 < NK) {             // prefetch next chunk, overlapped w/ compute
            load_stage(i + 1, (i + 1) & 1);
            cp_commit();
        }

        const uint32_t sb = sm0 + (i & 1) * STAGE_B;
        const uint32_t aBase = sb + (wm * 64 + a_row) * 128;
        const uint32_t bBase = sb + OFF_BH + (wn * 64 + b_row) * 128;

#pragma unroll
        for (int ks = 0; ks < 4; ks++) {
            const int cb = ks * 2;
#pragma unroll
            for (int mt = 0; mt < 4; mt++) {
                uint32_t ad = aBase + mt * 2048 + (((cb + a_c) ^ lr) << 4);
                ldsm_x4(ah[mt], ad);
            }
#pragma unroll
            for (int nt2 = 0; nt2 < 4; nt2++) {
                uint32_t bd = bBase + nt2 * 2048 + (((cb + b_c) ^ lr) << 4);
                ldsm_x4(bh[nt2], bd);
            }
#pragma unroll
            for (int mt = 0; mt < 4; mt++) {
#pragma unroll
                for (int nt = 0; nt < 8; nt++) {
                    const uint32_t* bhf = &bh[nt >> 1][(nt & 1) * 2];
                    mma_16816(acc[mt][nt], ah[mt], bhf);
                }
            }
        }
    }

    // Epilogue. acc map: d0,d1 = (row qr, cols 2qc,2qc+1); d2,d3 = row qr+8
    const int qr = lane >> 2;
    const int qc = lane & 3;
#pragma unroll
    for (int mt = 0; mt < 4; mt++) {
        const size_t m0 = (size_t)by * 128 + wm * 64 + mt * 16 + qr;
#pragma unroll
        for (int nt = 0; nt < 8; nt++) {
            const size_t n0 = (size_t)bx * 128 + wn * 64 + nt * 8 + qc * 2;
            const float* d = acc[mt][nt];
            if (GELU) {
                __half h0 = __float2half_rn(gelu_tanh(d[0]));
                __half h1 = __float2half_rn(gelu_tanh(d[1]));
                __half h2 = __float2half_rn(gelu_tanh(d[2]));
                __half h3 = __float2half_rn(gelu_tanh(d[3]));
                *reinterpret_cast<__half2*>(Ch + m0 * N + n0)       = __halves2half2(h0, h1);
                *reinterpret_cast<__half2*>(Ch + (m0 + 8) * N + n0) = __halves2half2(h2, h3);
            } else {
                float2 a0 = *reinterpret_cast<const float2*>(Madd + m0 * N + n0);
                float2 a1 = *reinterpret_cast<const float2*>(Madd + (m0 + 8) * N + n0);
                float2 v0; v0.x = d[0] + a0.x; v0.y = d[1] + a0.y;
                float2 v1; v1.x = d[2] + a1.x; v1.y = d[3] + a1.y;
                *reinterpret_cast<float2*>(Cf + m0 * N + n0)       = v0;
                *reinterpret_cast<float2*>(Cf + (m0 + 8) * N + n0) = v1;
            }
        }
    }
}

// ---------------------------------------------------------------------------
// Fused router + MoE: one block per token.
// Part 1: logits = x@rw, softmax (fp32), fp16 round-trip -> smem probs.
//         Also writes xh = fp16(x).
// Part 2: moe_out[n,h] = sum_e probs[e] * (cb[nibble]*std + mean).
// ---------------------------------------------------------------------------
__global__ __launch_bounds__(256) void router_moe_kernel(const float* __restrict__ x,
                                                         const float* __restrict__ rw,
                                                         const int* __restrict__ nf4,
                                                         const float* __restrict__ mean,
                                                         const float* __restrict__ stdv,
                                                         const float* __restrict__ cbg,
                                                         __half* __restrict__ xh,
                                                         float* __restrict__ moe_out)
{
    const int n = blockIdx.x;
    const int tid = threadIdx.x;
    __shared__ float sbuf[EEXP][256];
    __shared__ float pr[EEXP];
    __shared__ float cb[16];
    if (tid < 16) cb[tid] = cbg[tid];

    // --- router ---
    float acc[EEXP] = {0.f, 0.f, 0.f, 0.f, 0.f, 0.f, 0.f, 0.f};
    const float* xr = x + (size_t)n * HDIM;
    __half* xo = xh + (size_t)n * HDIM;
    for (int k = tid; k < HDIM; k += 256) {
        float xv = xr[k];
        xo[k] = __float2half_rn(xv);
        const float4* r4 = reinterpret_cast<const float4*>(rw + (size_t)k * EEXP);
        float4 a = r4[0];
        float4 b = r4[1];
        acc[0] = fmaf(xv, a.x, acc[0]); acc[1] = fmaf(xv, a.y, acc[1]);
        acc[2] = fmaf(xv, a.z, acc[2]); acc[3] = fmaf(xv, a.w, acc[3]);
        acc[4] = fmaf(xv, b.x, acc[4]); acc[5] = fmaf(xv, b.y, acc[5]);
        acc[6] = fmaf(xv, b.z, acc[6]); acc[7] = fmaf(xv, b.w, acc[7]);
    }
#pragma unroll
    for (int e = 0; e < EEXP; e++) sbuf[e][tid] = acc[e];
    __syncthreads();
    for (int s = 128; s > 0; s >>= 1) {
        if (tid < s) {
#pragma unroll
            for (int e = 0; e < EEXP; e++) sbuf[e][tid] += sbuf[e][tid + s];
        }
        __syncthreads();
    }
    if (tid == 0) {
        float l[EEXP];
        float mmax = -1e30f;
#pragma unroll
        for (int e = 0; e < EEXP; e++) { l[e] = sbuf[e][0]; mmax = fmaxf(mmax, l[e]); }
        float s = 0.f;
#pragma unroll
        for (int e = 0; e < EEXP; e++) { l[e] = expf(l[e] - mmax); s += l[e]; }
        float inv = 1.0f / s;
#pragma unroll
        for (int e = 0; e < EEXP; e++)
            pr[e] = __half2float(__float2half(l[e] * inv));
    }
    __syncthreads();

    // --- moe mix ---
    const int h0 = tid * 8;
    const int b = h0 >> 9;
    float macc[8] = {0.f, 0.f, 0.f, 0.f, 0.f, 0.f, 0.f, 0.f};
    const int4* base = reinterpret_cast<const int4*>(nf4 + (size_t)n * EEXP * (HDIM / 2)) + tid;
#pragma unroll
    for (int e = 0; e < EEXP; e++) {
        float p = pr[e];
        float sc = p * stdv[((size_t)n * EEXP + e) * 4 + b];
        float bi = p * mean[((size_t)n * EEXP + e) * 4 + b];
        int4 v = base[e * (HDIM / 2 / 4)];
        int vs[4] = {v.x, v.y, v.z, v.w};
#pragma unroll
        for (int j = 0; j < 4; j++) {
            macc[2 * j]     += fmaf(cb[vs[j] & 15], sc, bi);
            macc[2 * j + 1] += fmaf(cb[(vs[j] >> 4) & 15], sc, bi);
        }
    }
    float4* o = reinterpret_cast<float4*>(moe_out + (size_t)n * HDIM + h0);
    float4 o0, o1;
    o0.x = macc[0]; o0.y = macc[1]; o0.z = macc[2]; o0.w = macc[3];
    o1.x = macc[4]; o1.y = macc[5]; o1.z = macc[6]; o1.w = macc[7];
    o[0] = o0; o[1] = o1;
}

// ---------------------------------------------------------------------------
// Launch (single stream — graph-capture safe).
// inputs: 0:x 1:router_w 2:nf4 3:mean 4:std 5:codebook 6:w1 7:w2
// ---------------------------------------------------------------------------
extern "C" void kernel_launch(void* const* d_in, const int* in_sizes, int n_in,
                              void* d_out, int out_size)
{
    const float* x        = (const float*)d_in[0];
    const float* router_w = (const float*)d_in[1];
    const int*   nf4      = (const int*)d_in[2];
    const float* mean     = (const float*)d_in[3];
    const float* stdv     = (const float*)d_in[4];
    const float* codebook = (const float*)d_in[5];
    const float* w1       = (const float*)d_in[6];
    const float* w2       = (const float*)d_in[7];
    float* out = (float*)d_out;

    __half *xh, *w1h, *w2h, *h1h;
    float *moebuf;
    cudaGetSymbolAddress((void**)&xh,  g_xh);
    cudaGetSymbolAddress((void**)&w1h, g_w1h);
    cudaGetSymbolAddress((void**)&w2h, g_w2h);
    cudaGetSymbolAddress((void**)&h1h, g_h1h);
    cudaGetSymbolAddress((void**)&moebuf, g_moe);

    const int smem_bytes = 2 * STAGE_B;   // 64 KB
    cudaFuncSetAttribute(hgemm_kernel<true>,  cudaFuncAttributeMaxDynamicSharedMemorySize, smem_bytes);
    cudaFuncSetAttribute(hgemm_kernel<false>, cudaFuncAttributeMaxDynamicSharedMemorySize, smem_bytes);

    // fused router + x->fp16 + moe mix; weight transposes
    router_moe_kernel<<<NTOK, 256>>>(x, router_w, nf4, mean, stdv, codebook, xh, moebuf);
    transpose_half_kernel<<<dim3(DFF / 32, HDIM / 32), 256>>>(w1, w1h, HDIM, DFF);
    transpose_half_kernel<<<dim3(HDIM / 32, DFF / 32), 256>>>(w2, w2h, DFF, HDIM);

    // h1 = gelu(x @ w1) -> fp16   [4096 x 8192]  (32 M x 64 N tiles = 2048 CTAs)
    hgemm_kernel<true><<<(NTOK / 128) * (DFF / 128), 128, smem_bytes>>>(
        xh, w1h, h1h, nullptr, nullptr, DFF, HDIM);

    // out = h1 @ w2 + moe         [4096 x 2048]  (32 x 16 tiles = 512 CTAs)
    hgemm_kernel<false><<<(NTOK / 128) * (HDIM / 128), 128, smem_bytes>>>(
        h1h, w2h, nullptr, out, moebuf, HDIM, DFF);
}